// round 15
// baseline (speedup 1.0000x reference)
#include <cuda_runtime.h>
#include <cuda_fp16.h>
#include <math.h>
#include <stdint.h>

#define N_TOK 16384
#define D_DIM 1024
#define E_EXP 8
#define H_DIM 4096
#define CAP   3072            // int(1.5 * 16384 / 8)
#define EC    (E_EXP * CAP)   // 24576

// GEMM tiling (halves)
#define BM 128
#define BK 32                 // k-halves per stage (2 x k16 MMA steps)
#define ROWP 40               // row stride in halves (BK + 8 pad) -> conflict-free
#define NSTG 3
#define NT 256

#define A_HALF (BM * ROWP)            // 5120

// host-side smem sizes per BN
#define SMEM_OF(BN_) ((NSTG * (A_HALF + (BN_) * ROWP) * 2) + 512 + (BN_) * 4 + 128)

#define NLB 64                // loss partial blocks

// ---------------- scratch ----------------------------------------------------
__device__ __half g_h[(size_t)EC * H_DIM];                 // fp16 activations
__device__ __half g_xh[(size_t)N_TOK * D_DIM];             // fp16 x
__device__ __half g_W1t[(size_t)E_EXP * D_DIM * H_DIM];    // W1^T [e][H][D] fp16
__device__ __half g_W2t[(size_t)E_EXP * D_DIM * H_DIM];    // W2^T [e][D][H] fp16
__device__ int    g_tok[EC];
__device__ int    g_cnt[E_EXP];
__device__ float  g_probs[N_TOK * E_EXP];
__device__ float  g_gate[N_TOK];
__device__ int    g_gidx[N_TOK];
__device__ float  g_lpart[NLB][12];                        // [block][e0..7, l1]

// ---------------- helpers ----------------------------------------------------
__device__ __forceinline__ void cp16(uint32_t s, const void* g) {
    asm volatile("cp.async.cg.shared.global [%0], [%1], 16;" :: "r"(s), "l"(g));
}
__device__ __forceinline__ uint32_t smem_u32(const void* p) {
    return (uint32_t)__cvta_generic_to_shared(p);
}
__device__ __forceinline__ void mma_f16(float* d, const uint32_t* a, const uint32_t* b) {
    asm volatile(
        "mma.sync.aligned.m16n8k16.row.col.f32.f16.f16.f32 "
        "{%0,%1,%2,%3}, {%4,%5,%6,%7}, {%8,%9}, {%0,%1,%2,%3};"
        : "+f"(d[0]), "+f"(d[1]), "+f"(d[2]), "+f"(d[3])
        : "r"(a[0]), "r"(a[1]), "r"(a[2]), "r"(a[3]), "r"(b[0]), "r"(b[1]));
}

// ---------------- pre-pass: transpose W [e][R][C] -> fp16 [e][C][R] ----------
__global__ void transpose_half_kernel(const float* __restrict__ src,
                                      __half* __restrict__ dst, int R, int C) {
    __shared__ float t[32][33];
    int e = blockIdx.z;
    src += (size_t)e * R * C;
    dst += (size_t)e * R * C;
    int c0 = blockIdx.x * 32, r0 = blockIdx.y * 32;
    int tx = threadIdx.x, ty = threadIdx.y;   // 32 x 8
    #pragma unroll
    for (int j = 0; j < 4; j++)
        t[ty + 8 * j][tx] = src[(size_t)(r0 + ty + 8 * j) * C + c0 + tx];
    __syncthreads();
    #pragma unroll
    for (int j = 0; j < 4; j++)
        dst[(size_t)(c0 + ty + 8 * j) * R + r0 + tx] = __float2half_rn(t[tx][ty + 8 * j]);
}

// ---------------- router: float4 loads, immediate consume (high MLP) ---------
__global__ void router_kernel(const float* __restrict__ x,
                              const float* __restrict__ Wr,
                              const float* __restrict__ br) {
    int warp = (blockIdx.x * blockDim.x + threadIdx.x) >> 5;
    int lane = threadIdx.x & 31;
    if (warp >= N_TOK) return;
    const float4* xr4 = (const float4*)(x + (size_t)warp * D_DIM);

    float acc[E_EXP] = {0.f,0.f,0.f,0.f,0.f,0.f,0.f,0.f};
    #pragma unroll
    for (int j = 0; j < 8; j++) {
        float4 xv = xr4[lane + 32 * j];
        int r = 4 * (lane + 32 * j);
        float v[4] = {xv.x, xv.y, xv.z, xv.w};
        #pragma unroll
        for (int i = 0; i < 4; i++) {
            const float4* w = (const float4*)(Wr + (size_t)(r + i) * E_EXP);
            float4 w0 = w[0], w1 = w[1];
            acc[0] += v[i] * w0.x; acc[1] += v[i] * w0.y;
            acc[2] += v[i] * w0.z; acc[3] += v[i] * w0.w;
            acc[4] += v[i] * w1.x; acc[5] += v[i] * w1.y;
            acc[6] += v[i] * w1.z; acc[7] += v[i] * w1.w;
        }
    }
    #pragma unroll
    for (int e = 0; e < E_EXP; e++)
        #pragma unroll
        for (int off = 16; off; off >>= 1)
            acc[e] += __shfl_down_sync(0xffffffffu, acc[e], off);

    if (lane == 0) {
        float l[E_EXP];
        float m = -1e30f; int idx = 0;
        #pragma unroll
        for (int e = 0; e < E_EXP; e++) {
            l[e] = acc[e] + br[e];
            if (l[e] > m) { m = l[e]; idx = e; }   // first-max == argmax
        }
        float p[E_EXP], s = 0.f;
        #pragma unroll
        for (int e = 0; e < E_EXP; e++) { p[e] = expf(l[e] - m); s += p[e]; }
        float inv = 1.f / s;
        #pragma unroll
        for (int e = 0; e < E_EXP; e++) g_probs[warp * E_EXP + e] = p[e] * inv;
        g_gate[warp] = p[idx] * inv;
        g_gidx[warp] = idx;
    }
}

// ---------------- fused: out = x*gate, xh = fp16(x)  (one read of x) ---------
__global__ void scale_cvt_kernel(const float4* __restrict__ x,
                                 float4* __restrict__ out,
                                 __half2* __restrict__ xh) {
    int i = blockIdx.x * blockDim.x + threadIdx.x;   // float4 index
    float4 v = x[i];
    float g = g_gate[i >> 8];                         // 256 float4 per token
    out[i] = make_float4(v.x * g, v.y * g, v.z * g, v.w * g);
    xh[2 * i]     = __floats2half2_rn(v.x, v.y);
    xh[2 * i + 1] = __floats2half2_rn(v.z, v.w);
}

// ---------------- dispatch: warp-shuffle scan (same FIFO semantics) ----------
__global__ void dispatch_kernel() {
    __shared__ int woff[E_EXP][33];        // per-warp exclusive offsets
    int tid = threadIdx.x;
    int lane = tid & 31, wid = tid >> 5;   // 32 warps
    for (int i = tid; i < EC; i += 1024) g_tok[i] = N_TOK;

    int base = tid * 16;
    int ge[16];
    int lc[E_EXP] = {0,0,0,0,0,0,0,0};
    #pragma unroll
    for (int t = 0; t < 16; t++) { ge[t] = g_gidx[base + t]; lc[ge[t]]++; }

    // inclusive warp scan over threads (chunk order)
    int inc[E_EXP];
    #pragma unroll
    for (int e = 0; e < E_EXP; e++) {
        inc[e] = lc[e];
        #pragma unroll
        for (int off = 1; off < 32; off <<= 1) {
            int v = __shfl_up_sync(0xffffffffu, inc[e], off);
            if (lane >= off) inc[e] += v;
        }
        if (lane == 31) woff[e][wid] = inc[e];   // warp total
    }
    __syncthreads();

    // warp 0: exclusive scan of the 32 warp totals per expert
    if (wid == 0) {
        #pragma unroll
        for (int e = 0; e < E_EXP; e++) {
            int v = woff[e][lane];
            int iv = v;
            #pragma unroll
            for (int off = 1; off < 32; off <<= 1) {
                int u = __shfl_up_sync(0xffffffffu, iv, off);
                if (lane >= off) iv += u;
            }
            woff[e][lane] = iv - v;              // exclusive warp offset
            if (lane == 31) {
                int tot = iv;
                g_cnt[e] = (tot < CAP) ? tot : CAP;
            }
        }
    }
    __syncthreads();

    int pos[E_EXP];
    #pragma unroll
    for (int e = 0; e < E_EXP; e++) pos[e] = woff[e][wid] + inc[e] - lc[e];

    #pragma unroll
    for (int t = 0; t < 16; t++) {
        int e = ge[t];
        int p = pos[e]++;
        if (p < CAP) g_tok[e * CAP + p] = base + t;   // FIFO; overflow dropped
    }
}

// ---------------- fp16 mma.sync grouped GEMM (templated BN) ------------------
// FIRST: g_h[slot] = half(silu(gather(xh) @ W1t^T + b1))
// !FIRST: out[token] = (g_h @ W2t^T + b2) * gate  (scatter, skip pads)
template<int KDIM, int NDIM, int BN, bool FIRST>
__global__ __launch_bounds__(NT) void moe_gemm(const __half* __restrict__ Ag,
                                               const __half* __restrict__ Bg,
                                               const float* __restrict__ biasg,
                                               void* __restrict__ outg) {
    constexpr int BHALF = BN * ROWP;
    constexpr int STGH  = A_HALF + BHALF;          // halves per stage
    constexpr int STOKOFF = NSTG * STGH * 2;       // bytes
    constexpr int BIASOFF = STOKOFF + 512;
    constexpr int NTI = BN / 32;                   // n-tiles per warp (warp N = BN/4)
    constexpr int BITER = BN / 64;                 // B loader iterations

    extern __shared__ char smem[];
    const int e    = blockIdx.z;
    const int row0 = blockIdx.y * BM;
    if (row0 >= g_cnt[e]) return;            // all-pad tile

    const int col0 = blockIdx.x * BN;
    const int tid  = threadIdx.x;
    const int warp = tid >> 5, lane = tid & 31;
    const int wm = (warp >> 2) * 64;         // warp grid 2 (M) x 4 (N)
    const int wn = (warp & 3) * (BN / 4);
    const int fr = lane >> 2, fc = lane & 3;
    const uint32_t sb = smem_u32(smem);

    int*   stok  = (int*)(smem + STOKOFF);
    float* sbias = (float*)(smem + BIASOFF);
    if (tid < BM) stok[tid] = g_tok[e * CAP + row0 + tid];
    if (tid < BN) sbias[tid] = biasg[(size_t)e * NDIM + col0 + tid];
    __syncthreads();

    const __half* Be = Bg + (size_t)e * KDIM * NDIM + (size_t)col0 * KDIM;
    const __half* Ae = FIRST ? Ag : (Ag + (size_t)(e * CAP + row0) * KDIM);

    const int NS = KDIM / BK;

    auto load_stage = [&](int kt, int buf) {
        const uint32_t abase = sb + buf * (STGH * 2);
        const uint32_t bbase = abase + A_HALF * 2;
        const int k0 = kt * BK;
        #pragma unroll
        for (int i = 0; i < 2; i++) {                 // A: 128 rows x 4 seg16
            int lin = i * NT + tid;
            int r = lin >> 2, seg = lin & 3;
            const __half* g;
            if (FIRST) {
                int t = stok[r]; t = (t < N_TOK) ? t : 0;
                g = Ag + (size_t)t * KDIM + k0 + seg * 8;
            } else {
                g = Ae + (size_t)r * KDIM + k0 + seg * 8;
            }
            cp16(abase + r * (ROWP * 2) + seg * 16, g);
        }
        #pragma unroll
        for (int i = 0; i < BITER; i++) {             // B: BN rows x 4 seg16
            int lin = i * NT + tid;
            int r = lin >> 2, seg = lin & 3;
            cp16(bbase + r * (ROWP * 2) + seg * 16,
                 Be + (size_t)r * KDIM + k0 + seg * 8);
        }
        asm volatile("cp.async.commit_group;" ::: "memory");
    };

    float acc[4][NTI][4];
    #pragma unroll
    for (int mt = 0; mt < 4; mt++)
        #pragma unroll
        for (int nt = 0; nt < NTI; nt++)
            #pragma unroll
            for (int q = 0; q < 4; q++) acc[mt][nt][q] = 0.f;

    load_stage(0, 0);
    load_stage(1, 1);

    for (int kt = 0; kt < NS; kt++) {
        const int buf = kt % NSTG;
        if (kt + 2 < NS) {
            load_stage(kt + 2, (kt + 2) % NSTG);
            asm volatile("cp.async.wait_group 2;" ::: "memory");
        } else if (kt + 1 < NS) {
            asm volatile("cp.async.wait_group 1;" ::: "memory");
        } else {
            asm volatile("cp.async.wait_group 0;" ::: "memory");
        }
        __syncthreads();

        const uint32_t* Asw = (const uint32_t*)(smem + buf * (STGH * 2));
        const uint32_t* Bsw = Asw + A_HALF / 2;       // word (half2) indexing

        #pragma unroll
        for (int kk = 0; kk < 2; kk++) {
            const int kw = kk * 8;                    // k16 step in words
            uint32_t af[4][4], bf[NTI][2];
            #pragma unroll
            for (int mt = 0; mt < 4; mt++) {
                int base = (wm + mt * 16 + fr) * (ROWP / 2) + kw + fc;
                af[mt][0] = Asw[base];
                af[mt][1] = Asw[base + 8 * (ROWP / 2)];
                af[mt][2] = Asw[base + 4];
                af[mt][3] = Asw[base + 8 * (ROWP / 2) + 4];
            }
            #pragma unroll
            for (int nt = 0; nt < NTI; nt++) {
                int nb = (wn + nt * 8 + fr) * (ROWP / 2) + kw + fc;
                bf[nt][0] = Bsw[nb];
                bf[nt][1] = Bsw[nb + 4];
            }
            #pragma unroll
            for (int mt = 0; mt < 4; mt++)
                #pragma unroll
                for (int nt = 0; nt < NTI; nt++)
                    mma_f16(acc[mt][nt], af[mt], bf[nt]);
        }
        __syncthreads();
    }

    // ---- epilogue ----
    #pragma unroll
    for (int mt = 0; mt < 4; mt++) {
        #pragma unroll
        for (int half = 0; half < 2; half++) {
            const int rl = wm + mt * 16 + fr + half * 8;
            if (FIRST) {
                __half* hp = (__half*)outg + (size_t)(e * CAP + row0 + rl) * NDIM + col0;
                #pragma unroll
                for (int nt = 0; nt < NTI; nt++) {
                    int cc = wn + nt * 8 + 2 * fc;
                    float t0 = acc[mt][nt][half * 2 + 0] + sbias[cc];
                    float t1 = acc[mt][nt][half * 2 + 1] + sbias[cc + 1];
                    *(__half2*)(hp + cc) =
                        __floats2half2_rn(t0 / (1.f + expf(-t0)),
                                          t1 / (1.f + expf(-t1)));
                }
            } else {
                int tok = stok[rl];
                if (tok < N_TOK) {
                    float gv = g_gate[tok];
                    float* op = (float*)outg + (size_t)tok * NDIM + col0;
                    #pragma unroll
                    for (int nt = 0; nt < NTI; nt++) {
                        int cc = wn + nt * 8 + 2 * fc;
                        float2 v;
                        v.x = (acc[mt][nt][half * 2 + 0] + sbias[cc]) * gv;
                        v.y = (acc[mt][nt][half * 2 + 1] + sbias[cc + 1]) * gv;
                        *(float2*)(op + cc) = v;
                    }
                }
            }
        }
    }
}

// ---------------- aux losses: 2-phase deterministic reduction ----------------
__global__ void loss_part_kernel() {
    __shared__ float simp[E_EXP][256];
    __shared__ float sl1[256];
    int tid = threadIdx.x;
    int t0 = blockIdx.x * (N_TOK / NLB);
    float imp[E_EXP] = {0.f,0.f,0.f,0.f,0.f,0.f,0.f,0.f};
    float l1 = 0.f;
    for (int i = tid; i < N_TOK / NLB; i += 256) {
        const float4* p4 = (const float4*)(g_probs + (size_t)(t0 + i) * E_EXP);
        float4 a = p4[0], b = p4[1];
        imp[0] += a.x; imp[1] += a.y; imp[2] += a.z; imp[3] += a.w;
        imp[4] += b.x; imp[5] += b.y; imp[6] += b.z; imp[7] += b.w;
        l1 += a.x + a.y + a.z + a.w + b.x + b.y + b.z + b.w;
    }
    #pragma unroll
    for (int e = 0; e < E_EXP; e++) simp[e][tid] = imp[e];
    sl1[tid] = l1;
    __syncthreads();
    for (int off = 128; off; off >>= 1) {
        if (tid < off) {
            #pragma unroll
            for (int e = 0; e < E_EXP; e++) simp[e][tid] += simp[e][tid + off];
            sl1[tid] += sl1[tid + off];
        }
        __syncthreads();
    }
    if (tid == 0) {
        #pragma unroll
        for (int e = 0; e < E_EXP; e++) g_lpart[blockIdx.x][e] = simp[e][0];
        g_lpart[blockIdx.x][8] = sl1[0];
    }
}

__global__ void loss_final_kernel(float* __restrict__ out, int out_size) {
    if (threadIdx.x != 0 || out_size < N_TOK * D_DIM + 2) return;
    float imp[E_EXP] = {0.f,0.f,0.f,0.f,0.f,0.f,0.f,0.f};
    float l1 = 0.f;
    for (int b = 0; b < NLB; b++) {          // fixed order: deterministic
        #pragma unroll
        for (int e = 0; e < E_EXP; e++) imp[e] += g_lpart[b][e];
        l1 += g_lpart[b][8];
    }
    float mean = 0.f;
    #pragma unroll
    for (int e = 0; e < E_EXP; e++) mean += imp[e];
    mean *= (1.f / E_EXP);
    float var = 0.f;
    #pragma unroll
    for (int e = 0; e < E_EXP; e++) { float d = imp[e] - mean; var += d * d; }
    var *= (1.f / E_EXP);
    out[N_TOK * D_DIM]     = l1 / (float)N_TOK;
    out[N_TOK * D_DIM + 1] = var / (mean * mean);
}

// ---------------- launch: R12 forked-stream schedule -------------------------
extern "C" void kernel_launch(void* const* d_in, const int* in_sizes, int n_in,
                              void* d_out, int out_size) {
    const float* x  = (const float*)d_in[0];
    const float* Wr = (const float*)d_in[1];
    const float* br = (const float*)d_in[2];
    const float* W1 = (const float*)d_in[3];
    const float* b1 = (const float*)d_in[4];
    const float* W2 = (const float*)d_in[5];
    const float* b2 = (const float*)d_in[6];
    float* out = (float*)d_out;

    constexpr int SMEM1 = SMEM_OF(256);      // 93696
    constexpr int SMEM2 = SMEM_OF(128);      // 62592

    // one-time setup (first call is the uncaptured correctness run)
    static cudaStream_t sB = nullptr, sC = nullptr;
    static cudaEvent_t evF = nullptr, evB = nullptr, evR = nullptr, evC = nullptr;
    if (!sB) {
        cudaStreamCreateWithFlags(&sB, cudaStreamNonBlocking);
        cudaStreamCreateWithFlags(&sC, cudaStreamNonBlocking);
        cudaEventCreateWithFlags(&evF, cudaEventDisableTiming);
        cudaEventCreateWithFlags(&evB, cudaEventDisableTiming);
        cudaEventCreateWithFlags(&evR, cudaEventDisableTiming);
        cudaEventCreateWithFlags(&evC, cudaEventDisableTiming);
        cudaFuncSetAttribute(moe_gemm<D_DIM, H_DIM, 256, true>,
                             cudaFuncAttributeMaxDynamicSharedMemorySize, SMEM1);
        cudaFuncSetAttribute(moe_gemm<H_DIM, D_DIM, 128, false>,
                             cudaFuncAttributeMaxDynamicSharedMemorySize, SMEM2);
    }

    __half* g_xh_p;  cudaGetSymbolAddress((void**)&g_xh_p,  g_xh);
    __half* g_W1t_p; cudaGetSymbolAddress((void**)&g_W1t_p, g_W1t);
    __half* g_W2t_p; cudaGetSymbolAddress((void**)&g_W2t_p, g_W2t);
    __half* g_h_p;   cudaGetSymbolAddress((void**)&g_h_p,   g_h);

    // fork stream B: weight transposes (independent of x-path)
    cudaEventRecord(evF, 0);
    cudaStreamWaitEvent(sB, evF, 0);
    {
        dim3 g(H_DIM / 32, D_DIM / 32, E_EXP);
        transpose_half_kernel<<<g, dim3(32, 8), 0, sB>>>(W1, g_W1t_p, D_DIM, H_DIM);
    }
    {
        dim3 g(D_DIM / 32, H_DIM / 32, E_EXP);
        transpose_half_kernel<<<g, dim3(32, 8), 0, sB>>>(W2, g_W2t_p, H_DIM, D_DIM);
    }
    cudaEventRecord(evB, sB);

    // main stream: router
    router_kernel<<<N_TOK / 8, 256>>>(x, Wr, br);

    // fork stream C after router: dispatch + loss partials (1-block / tiny)
    cudaEventRecord(evR, 0);
    cudaStreamWaitEvent(sC, evR, 0);
    dispatch_kernel<<<1, 1024, 0, sC>>>();
    loss_part_kernel<<<NLB, 256, 0, sC>>>();
    cudaEventRecord(evC, sC);

    // main stream: scale_cvt overlaps dispatch/loss and transposes
    scale_cvt_kernel<<<(N_TOK * (D_DIM / 4)) / 256, 256>>>(
        (const float4*)x, (float4*)out, (__half2*)g_xh_p);

    // join before GEMMs
    cudaStreamWaitEvent(0, evB, 0);
    cudaStreamWaitEvent(0, evC, 0);

    {
        dim3 g(H_DIM / 256, CAP / BM, E_EXP);    // (16, 24, 8)
        moe_gemm<D_DIM, H_DIM, 256, true><<<g, NT, SMEM1>>>(g_xh_p, g_W1t_p, b1, g_h_p);
    }
    {
        dim3 g(D_DIM / 128, CAP / BM, E_EXP);    // (8, 24, 8)
        moe_gemm<H_DIM, D_DIM, 128, false><<<g, NT, SMEM2>>>(g_h_p, g_W2t_p, b2, out);
    }

    loss_final_kernel<<<1, 32>>>(out, out_size);
}

// round 16
// speedup vs baseline: 1.0630x; 1.0630x over previous
#include <cuda_runtime.h>
#include <cuda_fp16.h>
#include <math.h>
#include <stdint.h>

#define N_TOK 16384
#define D_DIM 1024
#define E_EXP 8
#define H_DIM 4096
#define CAP   3072            // int(1.5 * 16384 / 8)
#define EC    (E_EXP * CAP)   // 24576

// GEMM tiling (halves)
#define BM 128
#define BK 32                 // k-halves per stage (2 x k16 MMA steps)
#define ROWP 40               // row stride in halves (BK + 8 pad) -> conflict-free
#define NSTG 3
#define NT 256

#define A_HALF (BM * ROWP)            // 5120

// host-side smem sizes per BN
#define SMEM_OF(BN_) ((NSTG * (A_HALF + (BN_) * ROWP) * 2) + 512 + (BN_) * 4 + 128)

#define NLB 64                // loss partial blocks

// ---------------- scratch ----------------------------------------------------
__device__ __half g_h[(size_t)EC * H_DIM];                 // fp16 activations
__device__ __half g_xh[(size_t)N_TOK * D_DIM];             // fp16 x
__device__ __half g_W1t[(size_t)E_EXP * D_DIM * H_DIM];    // W1^T [e][H][D] fp16
__device__ __half g_W2t[(size_t)E_EXP * D_DIM * H_DIM];    // W2^T [e][D][H] fp16
__device__ int    g_tok[EC];
__device__ int    g_cnt[E_EXP];
__device__ float  g_probs[N_TOK * E_EXP];
__device__ float  g_gate[N_TOK];
__device__ int    g_gidx[N_TOK];
__device__ float  g_lpart[NLB][12];                        // [block][e0..7, l1]

// ---------------- helpers ----------------------------------------------------
__device__ __forceinline__ void cp16(uint32_t s, const void* g) {
    asm volatile("cp.async.cg.shared.global [%0], [%1], 16;" :: "r"(s), "l"(g));
}
__device__ __forceinline__ uint32_t smem_u32(const void* p) {
    return (uint32_t)__cvta_generic_to_shared(p);
}
__device__ __forceinline__ void mma_f16(float* d, const uint32_t* a, const uint32_t* b) {
    asm volatile(
        "mma.sync.aligned.m16n8k16.row.col.f32.f16.f16.f32 "
        "{%0,%1,%2,%3}, {%4,%5,%6,%7}, {%8,%9}, {%0,%1,%2,%3};"
        : "+f"(d[0]), "+f"(d[1]), "+f"(d[2]), "+f"(d[3])
        : "r"(a[0]), "r"(a[1]), "r"(a[2]), "r"(a[3]), "r"(b[0]), "r"(b[1]));
}

// ---------------- pre-pass: transpose W [e][R][C] -> fp16 [e][C][R] ----------
__global__ void transpose_half_kernel(const float* __restrict__ src,
                                      __half* __restrict__ dst, int R, int C) {
    __shared__ float t[32][33];
    int e = blockIdx.z;
    src += (size_t)e * R * C;
    dst += (size_t)e * R * C;
    int c0 = blockIdx.x * 32, r0 = blockIdx.y * 32;
    int tx = threadIdx.x, ty = threadIdx.y;   // 32 x 8
    #pragma unroll
    for (int j = 0; j < 4; j++)
        t[ty + 8 * j][tx] = src[(size_t)(r0 + ty + 8 * j) * C + c0 + tx];
    __syncthreads();
    #pragma unroll
    for (int j = 0; j < 4; j++)
        dst[(size_t)(c0 + ty + 8 * j) * R + r0 + tx] = __float2half_rn(t[tx][ty + 8 * j]);
}

// ---------------- router (lean scalar version: 32 regs, 83% occ) -------------
__global__ void router_kernel(const float* __restrict__ x,
                              const float* __restrict__ Wr,
                              const float* __restrict__ br) {
    int warp = (blockIdx.x * blockDim.x + threadIdx.x) >> 5;
    int lane = threadIdx.x & 31;
    if (warp >= N_TOK) return;
    const float* xr = x + (size_t)warp * D_DIM;

    float acc[E_EXP] = {0.f,0.f,0.f,0.f,0.f,0.f,0.f,0.f};
    #pragma unroll 8
    for (int j = 0; j < D_DIM / 32; j++) {
        float xv = xr[lane + 32 * j];
        const float4* w = (const float4*)(Wr + (size_t)(lane + 32 * j) * E_EXP);
        float4 w0 = w[0], w1 = w[1];
        acc[0] += xv * w0.x; acc[1] += xv * w0.y;
        acc[2] += xv * w0.z; acc[3] += xv * w0.w;
        acc[4] += xv * w1.x; acc[5] += xv * w1.y;
        acc[6] += xv * w1.z; acc[7] += xv * w1.w;
    }
    #pragma unroll
    for (int e = 0; e < E_EXP; e++)
        #pragma unroll
        for (int off = 16; off; off >>= 1)
            acc[e] += __shfl_down_sync(0xffffffffu, acc[e], off);

    if (lane == 0) {
        float l[E_EXP];
        float m = -1e30f; int idx = 0;
        #pragma unroll
        for (int e = 0; e < E_EXP; e++) {
            l[e] = acc[e] + br[e];
            if (l[e] > m) { m = l[e]; idx = e; }   // first-max == argmax
        }
        float p[E_EXP], s = 0.f;
        #pragma unroll
        for (int e = 0; e < E_EXP; e++) { p[e] = expf(l[e] - m); s += p[e]; }
        float inv = 1.f / s;
        #pragma unroll
        for (int e = 0; e < E_EXP; e++) g_probs[warp * E_EXP + e] = p[e] * inv;
        g_gate[warp] = p[idx] * inv;
        g_gidx[warp] = idx;
    }
}

// ---------------- fused: out = x*gate, xh = fp16(x)  (one read of x) ---------
__global__ void scale_cvt_kernel(const float4* __restrict__ x,
                                 float4* __restrict__ out,
                                 __half2* __restrict__ xh) {
    int i = blockIdx.x * blockDim.x + threadIdx.x;   // float4 index
    float4 v = x[i];
    float g = g_gate[i >> 8];                         // 256 float4 per token
    out[i] = make_float4(v.x * g, v.y * g, v.z * g, v.w * g);
    xh[2 * i]     = __floats2half2_rn(v.x, v.y);
    xh[2 * i + 1] = __floats2half2_rn(v.z, v.w);
}

// ---------------- dispatch: warp-shuffle scan (same FIFO semantics) ----------
__global__ void dispatch_kernel() {
    __shared__ int woff[E_EXP][33];        // per-warp exclusive offsets
    int tid = threadIdx.x;
    int lane = tid & 31, wid = tid >> 5;   // 32 warps
    for (int i = tid; i < EC; i += 1024) g_tok[i] = N_TOK;

    int base = tid * 16;
    int ge[16];
    int lc[E_EXP] = {0,0,0,0,0,0,0,0};
    #pragma unroll
    for (int t = 0; t < 16; t++) { ge[t] = g_gidx[base + t]; lc[ge[t]]++; }

    // inclusive warp scan over threads (chunk order)
    int inc[E_EXP];
    #pragma unroll
    for (int e = 0; e < E_EXP; e++) {
        inc[e] = lc[e];
        #pragma unroll
        for (int off = 1; off < 32; off <<= 1) {
            int v = __shfl_up_sync(0xffffffffu, inc[e], off);
            if (lane >= off) inc[e] += v;
        }
        if (lane == 31) woff[e][wid] = inc[e];   // warp total
    }
    __syncthreads();

    // warp 0: exclusive scan of the 32 warp totals per expert
    if (wid == 0) {
        #pragma unroll
        for (int e = 0; e < E_EXP; e++) {
            int v = woff[e][lane];
            int iv = v;
            #pragma unroll
            for (int off = 1; off < 32; off <<= 1) {
                int u = __shfl_up_sync(0xffffffffu, iv, off);
                if (lane >= off) iv += u;
            }
            woff[e][lane] = iv - v;              // exclusive warp offset
            if (lane == 31) {
                int tot = iv;
                g_cnt[e] = (tot < CAP) ? tot : CAP;
            }
        }
    }
    __syncthreads();

    int pos[E_EXP];
    #pragma unroll
    for (int e = 0; e < E_EXP; e++) pos[e] = woff[e][wid] + inc[e] - lc[e];

    #pragma unroll
    for (int t = 0; t < 16; t++) {
        int e = ge[t];
        int p = pos[e]++;
        if (p < CAP) g_tok[e * CAP + p] = base + t;   // FIFO; overflow dropped
    }
}

// ---------------- fp16 mma.sync grouped GEMM (templated BN) ------------------
// FIRST: g_h[slot] = half(silu(gather(xh) @ W1t^T + b1))
// !FIRST: out[token] = (g_h @ W2t^T + b2) * gate  (scatter, skip pads)
template<int KDIM, int NDIM, int BN, bool FIRST>
__global__ __launch_bounds__(NT) void moe_gemm(const __half* __restrict__ Ag,
                                               const __half* __restrict__ Bg,
                                               const float* __restrict__ biasg,
                                               void* __restrict__ outg) {
    constexpr int BHALF = BN * ROWP;
    constexpr int STGH  = A_HALF + BHALF;          // halves per stage
    constexpr int STOKOFF = NSTG * STGH * 2;       // bytes
    constexpr int BIASOFF = STOKOFF + 512;
    constexpr int NTI = BN / 32;                   // n-tiles per warp (warp N = BN/4)
    constexpr int BITER = BN / 64;                 // B loader iterations

    extern __shared__ char smem[];
    const int e    = blockIdx.z;
    const int row0 = blockIdx.y * BM;
    if (row0 >= g_cnt[e]) return;            // all-pad tile

    const int col0 = blockIdx.x * BN;
    const int tid  = threadIdx.x;
    const int warp = tid >> 5, lane = tid & 31;
    const int wm = (warp >> 2) * 64;         // warp grid 2 (M) x 4 (N)
    const int wn = (warp & 3) * (BN / 4);
    const int fr = lane >> 2, fc = lane & 3;
    const uint32_t sb = smem_u32(smem);

    int*   stok  = (int*)(smem + STOKOFF);
    float* sbias = (float*)(smem + BIASOFF);
    if (tid < BM) stok[tid] = g_tok[e * CAP + row0 + tid];
    if (tid < BN) sbias[tid] = biasg[(size_t)e * NDIM + col0 + tid];
    __syncthreads();

    const __half* Be = Bg + (size_t)e * KDIM * NDIM + (size_t)col0 * KDIM;
    const __half* Ae = FIRST ? Ag : (Ag + (size_t)(e * CAP + row0) * KDIM);

    const int NS = KDIM / BK;

    auto load_stage = [&](int kt, int buf) {
        const uint32_t abase = sb + buf * (STGH * 2);
        const uint32_t bbase = abase + A_HALF * 2;
        const int k0 = kt * BK;
        #pragma unroll
        for (int i = 0; i < 2; i++) {                 // A: 128 rows x 4 seg16
            int lin = i * NT + tid;
            int r = lin >> 2, seg = lin & 3;
            const __half* g;
            if (FIRST) {
                int t = stok[r]; t = (t < N_TOK) ? t : 0;
                g = Ag + (size_t)t * KDIM + k0 + seg * 8;
            } else {
                g = Ae + (size_t)r * KDIM + k0 + seg * 8;
            }
            cp16(abase + r * (ROWP * 2) + seg * 16, g);
        }
        #pragma unroll
        for (int i = 0; i < BITER; i++) {             // B: BN rows x 4 seg16
            int lin = i * NT + tid;
            int r = lin >> 2, seg = lin & 3;
            cp16(bbase + r * (ROWP * 2) + seg * 16,
                 Be + (size_t)r * KDIM + k0 + seg * 8);
        }
        asm volatile("cp.async.commit_group;" ::: "memory");
    };

    float acc[4][NTI][4];
    #pragma unroll
    for (int mt = 0; mt < 4; mt++)
        #pragma unroll
        for (int nt = 0; nt < NTI; nt++)
            #pragma unroll
            for (int q = 0; q < 4; q++) acc[mt][nt][q] = 0.f;

    load_stage(0, 0);
    load_stage(1, 1);

    for (int kt = 0; kt < NS; kt++) {
        const int buf = kt % NSTG;
        if (kt + 2 < NS) {
            load_stage(kt + 2, (kt + 2) % NSTG);
            asm volatile("cp.async.wait_group 2;" ::: "memory");
        } else if (kt + 1 < NS) {
            asm volatile("cp.async.wait_group 1;" ::: "memory");
        } else {
            asm volatile("cp.async.wait_group 0;" ::: "memory");
        }
        __syncthreads();

        const uint32_t* Asw = (const uint32_t*)(smem + buf * (STGH * 2));
        const uint32_t* Bsw = Asw + A_HALF / 2;       // word (half2) indexing

        #pragma unroll
        for (int kk = 0; kk < 2; kk++) {
            const int kw = kk * 8;                    // k16 step in words
            uint32_t af[4][4], bf[NTI][2];
            #pragma unroll
            for (int mt = 0; mt < 4; mt++) {
                int base = (wm + mt * 16 + fr) * (ROWP / 2) + kw + fc;
                af[mt][0] = Asw[base];
                af[mt][1] = Asw[base + 8 * (ROWP / 2)];
                af[mt][2] = Asw[base + 4];
                af[mt][3] = Asw[base + 8 * (ROWP / 2) + 4];
            }
            #pragma unroll
            for (int nt = 0; nt < NTI; nt++) {
                int nb = (wn + nt * 8 + fr) * (ROWP / 2) + kw + fc;
                bf[nt][0] = Bsw[nb];
                bf[nt][1] = Bsw[nb + 4];
            }
            #pragma unroll
            for (int mt = 0; mt < 4; mt++)
                #pragma unroll
                for (int nt = 0; nt < NTI; nt++)
                    mma_f16(acc[mt][nt], af[mt], bf[nt]);
        }
        __syncthreads();
    }

    // ---- epilogue ----
    #pragma unroll
    for (int mt = 0; mt < 4; mt++) {
        #pragma unroll
        for (int half = 0; half < 2; half++) {
            const int rl = wm + mt * 16 + fr + half * 8;
            if (FIRST) {
                __half* hp = (__half*)outg + (size_t)(e * CAP + row0 + rl) * NDIM + col0;
                #pragma unroll
                for (int nt = 0; nt < NTI; nt++) {
                    int cc = wn + nt * 8 + 2 * fc;
                    float t0 = acc[mt][nt][half * 2 + 0] + sbias[cc];
                    float t1 = acc[mt][nt][half * 2 + 1] + sbias[cc + 1];
                    *(__half2*)(hp + cc) =
                        __floats2half2_rn(t0 / (1.f + expf(-t0)),
                                          t1 / (1.f + expf(-t1)));
                }
            } else {
                int tok = stok[rl];
                if (tok < N_TOK) {
                    float gv = g_gate[tok];
                    float* op = (float*)outg + (size_t)tok * NDIM + col0;
                    #pragma unroll
                    for (int nt = 0; nt < NTI; nt++) {
                        int cc = wn + nt * 8 + 2 * fc;
                        float2 v;
                        v.x = (acc[mt][nt][half * 2 + 0] + sbias[cc]) * gv;
                        v.y = (acc[mt][nt][half * 2 + 1] + sbias[cc + 1]) * gv;
                        *(float2*)(op + cc) = v;
                    }
                }
            }
        }
    }
}

// ---------------- aux losses: 2-phase deterministic reduction ----------------
__global__ void loss_part_kernel() {
    __shared__ float simp[E_EXP][256];
    __shared__ float sl1[256];
    int tid = threadIdx.x;
    int t0 = blockIdx.x * (N_TOK / NLB);
    float imp[E_EXP] = {0.f,0.f,0.f,0.f,0.f,0.f,0.f,0.f};
    float l1 = 0.f;
    for (int i = tid; i < N_TOK / NLB; i += 256) {
        const float4* p4 = (const float4*)(g_probs + (size_t)(t0 + i) * E_EXP);
        float4 a = p4[0], b = p4[1];
        imp[0] += a.x; imp[1] += a.y; imp[2] += a.z; imp[3] += a.w;
        imp[4] += b.x; imp[5] += b.y; imp[6] += b.z; imp[7] += b.w;
        l1 += a.x + a.y + a.z + a.w + b.x + b.y + b.z + b.w;
    }
    #pragma unroll
    for (int e = 0; e < E_EXP; e++) simp[e][tid] = imp[e];
    sl1[tid] = l1;
    __syncthreads();
    for (int off = 128; off; off >>= 1) {
        if (tid < off) {
            #pragma unroll
            for (int e = 0; e < E_EXP; e++) simp[e][tid] += simp[e][tid + off];
            sl1[tid] += sl1[tid + off];
        }
        __syncthreads();
    }
    if (tid == 0) {
        #pragma unroll
        for (int e = 0; e < E_EXP; e++) g_lpart[blockIdx.x][e] = simp[e][0];
        g_lpart[blockIdx.x][8] = sl1[0];
    }
}

__global__ void loss_final_kernel(float* __restrict__ out, int out_size) {
    if (threadIdx.x != 0 || out_size < N_TOK * D_DIM + 2) return;
    float imp[E_EXP] = {0.f,0.f,0.f,0.f,0.f,0.f,0.f,0.f};
    float l1 = 0.f;
    for (int b = 0; b < NLB; b++) {          // fixed order: deterministic
        #pragma unroll
        for (int e = 0; e < E_EXP; e++) imp[e] += g_lpart[b][e];
        l1 += g_lpart[b][8];
    }
    float mean = 0.f;
    #pragma unroll
    for (int e = 0; e < E_EXP; e++) mean += imp[e];
    mean *= (1.f / E_EXP);
    float var = 0.f;
    #pragma unroll
    for (int e = 0; e < E_EXP; e++) { float d = imp[e] - mean; var += d * d; }
    var *= (1.f / E_EXP);
    out[N_TOK * D_DIM]     = l1 / (float)N_TOK;
    out[N_TOK * D_DIM + 1] = var / (mean * mean);
}

// ---------------- launch: R12 forked-stream schedule -------------------------
extern "C" void kernel_launch(void* const* d_in, const int* in_sizes, int n_in,
                              void* d_out, int out_size) {
    const float* x  = (const float*)d_in[0];
    const float* Wr = (const float*)d_in[1];
    const float* br = (const float*)d_in[2];
    const float* W1 = (const float*)d_in[3];
    const float* b1 = (const float*)d_in[4];
    const float* W2 = (const float*)d_in[5];
    const float* b2 = (const float*)d_in[6];
    float* out = (float*)d_out;

    constexpr int SMEM1 = SMEM_OF(256);      // 93696
    constexpr int SMEM2 = SMEM_OF(128);      // 62592

    // one-time setup (first call is the uncaptured correctness run)
    static cudaStream_t sB = nullptr, sC = nullptr;
    static cudaEvent_t evF = nullptr, evB = nullptr, evR = nullptr, evC = nullptr;
    if (!sB) {
        cudaStreamCreateWithFlags(&sB, cudaStreamNonBlocking);
        cudaStreamCreateWithFlags(&sC, cudaStreamNonBlocking);
        cudaEventCreateWithFlags(&evF, cudaEventDisableTiming);
        cudaEventCreateWithFlags(&evB, cudaEventDisableTiming);
        cudaEventCreateWithFlags(&evR, cudaEventDisableTiming);
        cudaEventCreateWithFlags(&evC, cudaEventDisableTiming);
        cudaFuncSetAttribute(moe_gemm<D_DIM, H_DIM, 256, true>,
                             cudaFuncAttributeMaxDynamicSharedMemorySize, SMEM1);
        cudaFuncSetAttribute(moe_gemm<H_DIM, D_DIM, 128, false>,
                             cudaFuncAttributeMaxDynamicSharedMemorySize, SMEM2);
    }

    __half* g_xh_p;  cudaGetSymbolAddress((void**)&g_xh_p,  g_xh);
    __half* g_W1t_p; cudaGetSymbolAddress((void**)&g_W1t_p, g_W1t);
    __half* g_W2t_p; cudaGetSymbolAddress((void**)&g_W2t_p, g_W2t);
    __half* g_h_p;   cudaGetSymbolAddress((void**)&g_h_p,   g_h);

    // fork stream B: weight transposes (independent of x-path)
    cudaEventRecord(evF, 0);
    cudaStreamWaitEvent(sB, evF, 0);
    {
        dim3 g(H_DIM / 32, D_DIM / 32, E_EXP);
        transpose_half_kernel<<<g, dim3(32, 8), 0, sB>>>(W1, g_W1t_p, D_DIM, H_DIM);
    }
    {
        dim3 g(D_DIM / 32, H_DIM / 32, E_EXP);
        transpose_half_kernel<<<g, dim3(32, 8), 0, sB>>>(W2, g_W2t_p, H_DIM, D_DIM);
    }
    cudaEventRecord(evB, sB);

    // main stream: router
    router_kernel<<<N_TOK / 8, 256>>>(x, Wr, br);

    // fork stream C after router: dispatch + loss partials (1-block / tiny)
    cudaEventRecord(evR, 0);
    cudaStreamWaitEvent(sC, evR, 0);
    dispatch_kernel<<<1, 1024, 0, sC>>>();
    loss_part_kernel<<<NLB, 256, 0, sC>>>();
    cudaEventRecord(evC, sC);

    // main stream: scale_cvt overlaps dispatch/loss and transposes
    scale_cvt_kernel<<<(N_TOK * (D_DIM / 4)) / 256, 256>>>(
        (const float4*)x, (float4*)out, (__half2*)g_xh_p);

    // join before GEMMs
    cudaStreamWaitEvent(0, evB, 0);
    cudaStreamWaitEvent(0, evC, 0);

    {
        dim3 g(H_DIM / 256, CAP / BM, E_EXP);    // (16, 24, 8)
        moe_gemm<D_DIM, H_DIM, 256, true><<<g, NT, SMEM1>>>(g_xh_p, g_W1t_p, b1, g_h_p);
    }
    {
        dim3 g(D_DIM / 128, CAP / BM, E_EXP);    // (8, 24, 8)
        moe_gemm<H_DIM, D_DIM, 128, false><<<g, NT, SMEM2>>>(g_h_p, g_W2t_p, b2, out);
    }

    loss_final_kernel<<<1, 32>>>(out, out_size);
}

// round 17
// speedup vs baseline: 1.1027x; 1.0373x over previous
#include <cuda_runtime.h>
#include <cuda_fp16.h>
#include <math.h>
#include <stdint.h>

#define N_TOK 16384
#define D_DIM 1024
#define E_EXP 8
#define H_DIM 4096
#define CAP   3072            // int(1.5 * 16384 / 8)
#define EC    (E_EXP * CAP)   // 24576

// GEMM tiling (halves)
#define BM 128
#define BK 32                 // k-halves per stage (2 x k16 MMA steps)
#define ROWP 40               // row stride in halves (BK + 8 pad) -> conflict-free
#define NSTG 3
#define NT 256

#define A_HALF (BM * ROWP)            // 5120

// host-side smem sizes per BN
#define SMEM_OF(BN_) ((NSTG * (A_HALF + (BN_) * ROWP) * 2) + 512 + (BN_) * 4 + 128)

#define NLB 64                // loss partial blocks

// ---------------- scratch ----------------------------------------------------
__device__ __half g_h[(size_t)EC * H_DIM];                 // fp16 activations
__device__ __half g_xh[(size_t)N_TOK * D_DIM];             // fp16 x
__device__ __half g_W1t[(size_t)E_EXP * D_DIM * H_DIM];    // W1^T [e][H][D] fp16
__device__ __half g_W2t[(size_t)E_EXP * D_DIM * H_DIM];    // W2^T [e][D][H] fp16
__device__ int    g_tok[EC];
__device__ int    g_cnt[E_EXP];
__device__ float  g_probs[N_TOK * E_EXP];
__device__ float  g_gate[N_TOK];
__device__ int    g_gidx[N_TOK];
__device__ float  g_lpart[NLB][12];                        // [block][e0..7, l1]

// ---------------- helpers ----------------------------------------------------
__device__ __forceinline__ void cp16(uint32_t s, const void* g) {
    asm volatile("cp.async.cg.shared.global [%0], [%1], 16;" :: "r"(s), "l"(g));
}
__device__ __forceinline__ uint32_t smem_u32(const void* p) {
    return (uint32_t)__cvta_generic_to_shared(p);
}
__device__ __forceinline__ void mma_f16(float* d, const uint32_t* a, const uint32_t* b) {
    asm volatile(
        "mma.sync.aligned.m16n8k16.row.col.f32.f16.f16.f32 "
        "{%0,%1,%2,%3}, {%4,%5,%6,%7}, {%8,%9}, {%0,%1,%2,%3};"
        : "+f"(d[0]), "+f"(d[1]), "+f"(d[2]), "+f"(d[3])
        : "r"(a[0]), "r"(a[1]), "r"(a[2]), "r"(a[3]), "r"(b[0]), "r"(b[1]));
}

// ---------------- pre-pass: transpose W [e][R][C] -> fp16 [e][C][R] ----------
__global__ void transpose_half_kernel(const float* __restrict__ src,
                                      __half* __restrict__ dst, int R, int C) {
    __shared__ float t[32][33];
    int e = blockIdx.z;
    src += (size_t)e * R * C;
    dst += (size_t)e * R * C;
    int c0 = blockIdx.x * 32, r0 = blockIdx.y * 32;
    int tx = threadIdx.x, ty = threadIdx.y;   // 32 x 8
    #pragma unroll
    for (int j = 0; j < 4; j++)
        t[ty + 8 * j][tx] = src[(size_t)(r0 + ty + 8 * j) * C + c0 + tx];
    __syncthreads();
    #pragma unroll
    for (int j = 0; j < 4; j++)
        dst[(size_t)(c0 + ty + 8 * j) * R + r0 + tx] = __float2half_rn(t[tx][ty + 8 * j]);
}

// ---------------- router (lean scalar version: 32 regs, 83% occ) -------------
__global__ void router_kernel(const float* __restrict__ x,
                              const float* __restrict__ Wr,
                              const float* __restrict__ br) {
    int warp = (blockIdx.x * blockDim.x + threadIdx.x) >> 5;
    int lane = threadIdx.x & 31;
    if (warp >= N_TOK) return;
    const float* xr = x + (size_t)warp * D_DIM;

    float acc[E_EXP] = {0.f,0.f,0.f,0.f,0.f,0.f,0.f,0.f};
    #pragma unroll 8
    for (int j = 0; j < D_DIM / 32; j++) {
        float xv = xr[lane + 32 * j];
        const float4* w = (const float4*)(Wr + (size_t)(lane + 32 * j) * E_EXP);
        float4 w0 = w[0], w1 = w[1];
        acc[0] += xv * w0.x; acc[1] += xv * w0.y;
        acc[2] += xv * w0.z; acc[3] += xv * w0.w;
        acc[4] += xv * w1.x; acc[5] += xv * w1.y;
        acc[6] += xv * w1.z; acc[7] += xv * w1.w;
    }
    #pragma unroll
    for (int e = 0; e < E_EXP; e++)
        #pragma unroll
        for (int off = 16; off; off >>= 1)
            acc[e] += __shfl_down_sync(0xffffffffu, acc[e], off);

    if (lane == 0) {
        float l[E_EXP];
        float m = -1e30f; int idx = 0;
        #pragma unroll
        for (int e = 0; e < E_EXP; e++) {
            l[e] = acc[e] + br[e];
            if (l[e] > m) { m = l[e]; idx = e; }   // first-max == argmax
        }
        float p[E_EXP], s = 0.f;
        #pragma unroll
        for (int e = 0; e < E_EXP; e++) { p[e] = expf(l[e] - m); s += p[e]; }
        float inv = 1.f / s;
        #pragma unroll
        for (int e = 0; e < E_EXP; e++) g_probs[warp * E_EXP + e] = p[e] * inv;
        g_gate[warp] = p[idx] * inv;
        g_gidx[warp] = idx;
    }
}

// ---------------- fused: out = x*gate, xh = fp16(x)  (one read of x) ---------
__global__ void scale_cvt_kernel(const float4* __restrict__ x,
                                 float4* __restrict__ out,
                                 __half2* __restrict__ xh) {
    int i = blockIdx.x * blockDim.x + threadIdx.x;   // float4 index
    float4 v = x[i];
    float g = g_gate[i >> 8];                         // 256 float4 per token
    out[i] = make_float4(v.x * g, v.y * g, v.z * g, v.w * g);
    xh[2 * i]     = __floats2half2_rn(v.x, v.y);
    xh[2 * i + 1] = __floats2half2_rn(v.z, v.w);
}

// ---------------- dispatch: warp-shuffle scan (same FIFO semantics) ----------
__global__ void dispatch_kernel() {
    __shared__ int woff[E_EXP][33];        // per-warp exclusive offsets
    int tid = threadIdx.x;
    int lane = tid & 31, wid = tid >> 5;   // 32 warps
    for (int i = tid; i < EC; i += 1024) g_tok[i] = N_TOK;

    int base = tid * 16;
    int ge[16];
    int lc[E_EXP] = {0,0,0,0,0,0,0,0};
    #pragma unroll
    for (int t = 0; t < 16; t++) { ge[t] = g_gidx[base + t]; lc[ge[t]]++; }

    // inclusive warp scan over threads (chunk order)
    int inc[E_EXP];
    #pragma unroll
    for (int e = 0; e < E_EXP; e++) {
        inc[e] = lc[e];
        #pragma unroll
        for (int off = 1; off < 32; off <<= 1) {
            int v = __shfl_up_sync(0xffffffffu, inc[e], off);
            if (lane >= off) inc[e] += v;
        }
        if (lane == 31) woff[e][wid] = inc[e];   // warp total
    }
    __syncthreads();

    // warp 0: exclusive scan of the 32 warp totals per expert
    if (wid == 0) {
        #pragma unroll
        for (int e = 0; e < E_EXP; e++) {
            int v = woff[e][lane];
            int iv = v;
            #pragma unroll
            for (int off = 1; off < 32; off <<= 1) {
                int u = __shfl_up_sync(0xffffffffu, iv, off);
                if (lane >= off) iv += u;
            }
            woff[e][lane] = iv - v;              // exclusive warp offset
            if (lane == 31) {
                int tot = iv;
                g_cnt[e] = (tot < CAP) ? tot : CAP;
            }
        }
    }
    __syncthreads();

    int pos[E_EXP];
    #pragma unroll
    for (int e = 0; e < E_EXP; e++) pos[e] = woff[e][wid] + inc[e] - lc[e];

    #pragma unroll
    for (int t = 0; t < 16; t++) {
        int e = ge[t];
        int p = pos[e]++;
        if (p < CAP) g_tok[e * CAP + p] = base + t;   // FIFO; overflow dropped
    }
}

// ---------------- fp16 mma.sync grouped GEMM (templated BN, MINB) ------------
// FIRST: g_h[slot] = half(silu(gather(xh) @ W1t^T + b1))
// !FIRST: out[token] = (g_h @ W2t^T + b2) * gate  (scatter, skip pads)
// MINB=2 (GEMM2 only): cap regs to fit 2 CTAs/SM for latency hiding.
template<int KDIM, int NDIM, int BN, bool FIRST, int MINB>
__global__ __launch_bounds__(NT, MINB) void moe_gemm(const __half* __restrict__ Ag,
                                                     const __half* __restrict__ Bg,
                                                     const float* __restrict__ biasg,
                                                     void* __restrict__ outg) {
    constexpr int BHALF = BN * ROWP;
    constexpr int STGH  = A_HALF + BHALF;          // halves per stage
    constexpr int STOKOFF = NSTG * STGH * 2;       // bytes
    constexpr int BIASOFF = STOKOFF + 512;
    constexpr int NTI = BN / 32;                   // n-tiles per warp (warp N = BN/4)
    constexpr int BITER = BN / 64;                 // B loader iterations

    extern __shared__ char smem[];
    const int e    = blockIdx.z;
    const int row0 = blockIdx.y * BM;
    if (row0 >= g_cnt[e]) return;            // all-pad tile

    const int col0 = blockIdx.x * BN;
    const int tid  = threadIdx.x;
    const int warp = tid >> 5, lane = tid & 31;
    const int wm = (warp >> 2) * 64;         // warp grid 2 (M) x 4 (N)
    const int wn = (warp & 3) * (BN / 4);
    const int fr = lane >> 2, fc = lane & 3;
    const uint32_t sb = smem_u32(smem);

    int*   stok  = (int*)(smem + STOKOFF);
    float* sbias = (float*)(smem + BIASOFF);
    if (tid < BM) stok[tid] = g_tok[e * CAP + row0 + tid];
    if (tid < BN) sbias[tid] = biasg[(size_t)e * NDIM + col0 + tid];
    __syncthreads();

    const __half* Be = Bg + (size_t)e * KDIM * NDIM + (size_t)col0 * KDIM;
    const __half* Ae = FIRST ? Ag : (Ag + (size_t)(e * CAP + row0) * KDIM);

    const int NS = KDIM / BK;

    auto load_stage = [&](int kt, int buf) {
        const uint32_t abase = sb + buf * (STGH * 2);
        const uint32_t bbase = abase + A_HALF * 2;
        const int k0 = kt * BK;
        #pragma unroll
        for (int i = 0; i < 2; i++) {                 // A: 128 rows x 4 seg16
            int lin = i * NT + tid;
            int r = lin >> 2, seg = lin & 3;
            const __half* g;
            if (FIRST) {
                int t = stok[r]; t = (t < N_TOK) ? t : 0;
                g = Ag + (size_t)t * KDIM + k0 + seg * 8;
            } else {
                g = Ae + (size_t)r * KDIM + k0 + seg * 8;
            }
            cp16(abase + r * (ROWP * 2) + seg * 16, g);
        }
        #pragma unroll
        for (int i = 0; i < BITER; i++) {             // B: BN rows x 4 seg16
            int lin = i * NT + tid;
            int r = lin >> 2, seg = lin & 3;
            cp16(bbase + r * (ROWP * 2) + seg * 16,
                 Be + (size_t)r * KDIM + k0 + seg * 8);
        }
        asm volatile("cp.async.commit_group;" ::: "memory");
    };

    float acc[4][NTI][4];
    #pragma unroll
    for (int mt = 0; mt < 4; mt++)
        #pragma unroll
        for (int nt = 0; nt < NTI; nt++)
            #pragma unroll
            for (int q = 0; q < 4; q++) acc[mt][nt][q] = 0.f;

    load_stage(0, 0);
    load_stage(1, 1);

    for (int kt = 0; kt < NS; kt++) {
        const int buf = kt % NSTG;
        if (kt + 2 < NS) {
            load_stage(kt + 2, (kt + 2) % NSTG);
            asm volatile("cp.async.wait_group 2;" ::: "memory");
        } else if (kt + 1 < NS) {
            asm volatile("cp.async.wait_group 1;" ::: "memory");
        } else {
            asm volatile("cp.async.wait_group 0;" ::: "memory");
        }
        __syncthreads();

        const uint32_t* Asw = (const uint32_t*)(smem + buf * (STGH * 2));
        const uint32_t* Bsw = Asw + A_HALF / 2;       // word (half2) indexing

        #pragma unroll
        for (int kk = 0; kk < 2; kk++) {
            const int kw = kk * 8;                    // k16 step in words
            uint32_t af[4][4], bf[NTI][2];
            #pragma unroll
            for (int mt = 0; mt < 4; mt++) {
                int base = (wm + mt * 16 + fr) * (ROWP / 2) + kw + fc;
                af[mt][0] = Asw[base];
                af[mt][1] = Asw[base + 8 * (ROWP / 2)];
                af[mt][2] = Asw[base + 4];
                af[mt][3] = Asw[base + 8 * (ROWP / 2) + 4];
            }
            #pragma unroll
            for (int nt = 0; nt < NTI; nt++) {
                int nb = (wn + nt * 8 + fr) * (ROWP / 2) + kw + fc;
                bf[nt][0] = Bsw[nb];
                bf[nt][1] = Bsw[nb + 4];
            }
            #pragma unroll
            for (int mt = 0; mt < 4; mt++)
                #pragma unroll
                for (int nt = 0; nt < NTI; nt++)
                    mma_f16(acc[mt][nt], af[mt], bf[nt]);
        }
        __syncthreads();
    }

    // ---- epilogue ----
    #pragma unroll
    for (int mt = 0; mt < 4; mt++) {
        #pragma unroll
        for (int half = 0; half < 2; half++) {
            const int rl = wm + mt * 16 + fr + half * 8;
            if (FIRST) {
                __half* hp = (__half*)outg + (size_t)(e * CAP + row0 + rl) * NDIM + col0;
                #pragma unroll
                for (int nt = 0; nt < NTI; nt++) {
                    int cc = wn + nt * 8 + 2 * fc;
                    float t0 = acc[mt][nt][half * 2 + 0] + sbias[cc];
                    float t1 = acc[mt][nt][half * 2 + 1] + sbias[cc + 1];
                    *(__half2*)(hp + cc) =
                        __floats2half2_rn(t0 / (1.f + expf(-t0)),
                                          t1 / (1.f + expf(-t1)));
                }
            } else {
                int tok = stok[rl];
                if (tok < N_TOK) {
                    float gv = g_gate[tok];
                    float* op = (float*)outg + (size_t)tok * NDIM + col0;
                    #pragma unroll
                    for (int nt = 0; nt < NTI; nt++) {
                        int cc = wn + nt * 8 + 2 * fc;
                        float2 v;
                        v.x = (acc[mt][nt][half * 2 + 0] + sbias[cc]) * gv;
                        v.y = (acc[mt][nt][half * 2 + 1] + sbias[cc + 1]) * gv;
                        *(float2*)(op + cc) = v;
                    }
                }
            }
        }
    }
}

// ---------------- aux losses: 2-phase deterministic reduction ----------------
__global__ void loss_part_kernel() {
    __shared__ float simp[E_EXP][256];
    __shared__ float sl1[256];
    int tid = threadIdx.x;
    int t0 = blockIdx.x * (N_TOK / NLB);
    float imp[E_EXP] = {0.f,0.f,0.f,0.f,0.f,0.f,0.f,0.f};
    float l1 = 0.f;
    for (int i = tid; i < N_TOK / NLB; i += 256) {
        const float4* p4 = (const float4*)(g_probs + (size_t)(t0 + i) * E_EXP);
        float4 a = p4[0], b = p4[1];
        imp[0] += a.x; imp[1] += a.y; imp[2] += a.z; imp[3] += a.w;
        imp[4] += b.x; imp[5] += b.y; imp[6] += b.z; imp[7] += b.w;
        l1 += a.x + a.y + a.z + a.w + b.x + b.y + b.z + b.w;
    }
    #pragma unroll
    for (int e = 0; e < E_EXP; e++) simp[e][tid] = imp[e];
    sl1[tid] = l1;
    __syncthreads();
    for (int off = 128; off; off >>= 1) {
        if (tid < off) {
            #pragma unroll
            for (int e = 0; e < E_EXP; e++) simp[e][tid] += simp[e][tid + off];
            sl1[tid] += sl1[tid + off];
        }
        __syncthreads();
    }
    if (tid == 0) {
        #pragma unroll
        for (int e = 0; e < E_EXP; e++) g_lpart[blockIdx.x][e] = simp[e][0];
        g_lpart[blockIdx.x][8] = sl1[0];
    }
}

__global__ void loss_final_kernel(float* __restrict__ out, int out_size) {
    if (threadIdx.x != 0 || out_size < N_TOK * D_DIM + 2) return;
    float imp[E_EXP] = {0.f,0.f,0.f,0.f,0.f,0.f,0.f,0.f};
    float l1 = 0.f;
    for (int b = 0; b < NLB; b++) {          // fixed order: deterministic
        #pragma unroll
        for (int e = 0; e < E_EXP; e++) imp[e] += g_lpart[b][e];
        l1 += g_lpart[b][8];
    }
    float mean = 0.f;
    #pragma unroll
    for (int e = 0; e < E_EXP; e++) mean += imp[e];
    mean *= (1.f / E_EXP);
    float var = 0.f;
    #pragma unroll
    for (int e = 0; e < E_EXP; e++) { float d = imp[e] - mean; var += d * d; }
    var *= (1.f / E_EXP);
    out[N_TOK * D_DIM]     = l1 / (float)N_TOK;
    out[N_TOK * D_DIM + 1] = var / (mean * mean);
}

// ---------------- launch: R12 forked-stream schedule -------------------------
extern "C" void kernel_launch(void* const* d_in, const int* in_sizes, int n_in,
                              void* d_out, int out_size) {
    const float* x  = (const float*)d_in[0];
    const float* Wr = (const float*)d_in[1];
    const float* br = (const float*)d_in[2];
    const float* W1 = (const float*)d_in[3];
    const float* b1 = (const float*)d_in[4];
    const float* W2 = (const float*)d_in[5];
    const float* b2 = (const float*)d_in[6];
    float* out = (float*)d_out;

    constexpr int SMEM1 = SMEM_OF(256);      // 93696
    constexpr int SMEM2 = SMEM_OF(128);      // 62592

    // one-time setup (first call is the uncaptured correctness run)
    static cudaStream_t sB = nullptr, sC = nullptr;
    static cudaEvent_t evF = nullptr, evB = nullptr, evR = nullptr, evC = nullptr;
    if (!sB) {
        cudaStreamCreateWithFlags(&sB, cudaStreamNonBlocking);
        cudaStreamCreateWithFlags(&sC, cudaStreamNonBlocking);
        cudaEventCreateWithFlags(&evF, cudaEventDisableTiming);
        cudaEventCreateWithFlags(&evB, cudaEventDisableTiming);
        cudaEventCreateWithFlags(&evR, cudaEventDisableTiming);
        cudaEventCreateWithFlags(&evC, cudaEventDisableTiming);
        cudaFuncSetAttribute(moe_gemm<D_DIM, H_DIM, 256, true, 1>,
                             cudaFuncAttributeMaxDynamicSharedMemorySize, SMEM1);
        cudaFuncSetAttribute(moe_gemm<H_DIM, D_DIM, 128, false, 2>,
                             cudaFuncAttributeMaxDynamicSharedMemorySize, SMEM2);
    }

    __half* g_xh_p;  cudaGetSymbolAddress((void**)&g_xh_p,  g_xh);
    __half* g_W1t_p; cudaGetSymbolAddress((void**)&g_W1t_p, g_W1t);
    __half* g_W2t_p; cudaGetSymbolAddress((void**)&g_W2t_p, g_W2t);
    __half* g_h_p;   cudaGetSymbolAddress((void**)&g_h_p,   g_h);

    // fork stream B: weight transposes (independent of x-path)
    cudaEventRecord(evF, 0);
    cudaStreamWaitEvent(sB, evF, 0);
    {
        dim3 g(H_DIM / 32, D_DIM / 32, E_EXP);
        transpose_half_kernel<<<g, dim3(32, 8), 0, sB>>>(W1, g_W1t_p, D_DIM, H_DIM);
    }
    {
        dim3 g(D_DIM / 32, H_DIM / 32, E_EXP);
        transpose_half_kernel<<<g, dim3(32, 8), 0, sB>>>(W2, g_W2t_p, H_DIM, D_DIM);
    }
    cudaEventRecord(evB, sB);

    // main stream: router
    router_kernel<<<N_TOK / 8, 256>>>(x, Wr, br);

    // fork stream C after router: dispatch + loss (fully off critical path)
    cudaEventRecord(evR, 0);
    cudaStreamWaitEvent(sC, evR, 0);
    dispatch_kernel<<<1, 1024, 0, sC>>>();
    loss_part_kernel<<<NLB, 256, 0, sC>>>();
    loss_final_kernel<<<1, 32, 0, sC>>>(out, out_size);   // writes only scalar tail
    cudaEventRecord(evC, sC);

    // main stream: scale_cvt overlaps dispatch/loss and transposes
    scale_cvt_kernel<<<(N_TOK * (D_DIM / 4)) / 256, 256>>>(
        (const float4*)x, (float4*)out, (__half2*)g_xh_p);

    // join before GEMMs
    cudaStreamWaitEvent(0, evB, 0);
    cudaStreamWaitEvent(0, evC, 0);

    {
        dim3 g(H_DIM / 256, CAP / BM, E_EXP);    // (16, 24, 8)
        moe_gemm<D_DIM, H_DIM, 256, true, 1><<<g, NT, SMEM1>>>(g_xh_p, g_W1t_p, b1, g_h_p);
    }
    {
        dim3 g(D_DIM / 128, CAP / BM, E_EXP);    // (8, 24, 8)
        moe_gemm<H_DIM, D_DIM, 128, false, 2><<<g, NT, SMEM2>>>(g_h_p, g_W2t_p, b2, out);
    }
}